// round 12
// baseline (speedup 1.0000x reference)
#include <cuda_runtime.h>
#include <cuda_fp16.h>
#include <cstdint>

// ============================================================================
// T=1, h0=c0=0 => w_hh* unused, f-gate unused. Chain of small GEMMs on HMMA
// (mma.sync m16n8k16 fp16 -> f32 accum).
// R10 precision (kept): W = W_hi + W_lo fp16 (exact to 2^-22), A = fp16(x);
//   2 MMA passes give A*W exactly; only A-quantization dropped (~4e-5 final).
// R11 epilogue (kept): sig via tanh.approx => 4 MUFU + ~7 FMA per h.
// R12: ntj-lag software pipeline for L1..L4: MMA(ntj p) co-scheduled with
//   EPI(p-1) on double-buffered accumulators -> tensor & MUFU pipes overlap
//   instead of phase-convoying. Affordable now (fp16: 16 A regs + 48 accums).
//   L0 (KH=4) stays unpipelined to cap register pressure.
// Persistent: 148 CTAs x 512 thr; warp owns 32 rows, warp-private A smem.
// ============================================================================

#define NT    512
#define GRID  148
#define AP    272
#define WIMG  84096
#define WARP_ABUF (32 * AP)
#define SMEM_BYTES (WIMG + 16 * WARP_ABUF)

// stage bases (bytes); per LSTM stage: [IG groups][O frags], hi then lo kidx
#define WB_L0 0
#define WB_L1 24576
#define WB_L2 36864
#define WB_L3 49152
#define WB_L4 61440
#define WB_FC 73728
#define BIAS_OFF 81920

__device__ __align__(16) unsigned char g_img[WIMG];

// ---------------- fast math ----------------
__device__ __forceinline__ float tanhap(float x) {
    float y; asm("tanh.approx.f32 %0, %1;" : "=f"(y) : "f"(x)); return y;
}
__device__ __forceinline__ uint32_t packh2(float a, float b) {
    __half2 v = __float22half2_rn(make_float2(a, b));
    return *reinterpret_cast<uint32_t*>(&v);
}

// fused LSTM activation: h = sig(o)*tanh(sig(i)*tanh(g)).
// bi,bo arrive pre-scaled by 0.5; bg plain.
__device__ __forceinline__ float act_h(float ci, float cg, float co,
                                       float bi, float bg, float bo) {
    float si = fmaf(tanhap(fmaf(ci, 0.5f, bi)), 0.5f, 0.5f);
    float tg = tanhap(cg + bg);
    float tc = tanhap(si * tg);
    float so = fmaf(tanhap(fmaf(co, 0.5f, bo)), 0.5f, 0.5f);
    return so * tc;
}

// ---------------- mma (fp16 inputs, f32 accum) ----------------
__device__ __forceinline__ void mma_f16(float c[4],
    const uint32_t a[4], uint32_t b0, uint32_t b1) {
    asm volatile(
        "mma.sync.aligned.m16n8k16.row.col.f32.f16.f16.f32 "
        "{%0,%1,%2,%3},{%4,%5,%6,%7},{%8,%9},{%0,%1,%2,%3};"
        : "+f"(c[0]), "+f"(c[1]), "+f"(c[2]), "+f"(c[3])
        : "r"(a[0]), "r"(a[1]), "r"(a[2]), "r"(a[3]), "r"(b0), "r"(b1));
}

// ---------------- weight pack: v2 layout, fp16 hi/lo (R10) ----------------
// LSTM stage s (KH = 4 for L0 else 2): kidx 0..2KH-1 (hi then lo) x 4 ntj.
//   IG group (kidx,ntj) at base + (kidx*4+ntj)*512: per lane 16B = i0,i1,g0,g1
//   O frag at base + KH*4096 + (kidx*4+ntj)*256: per lane 8B = o0,o1
// FC: kidx 0..3 (2 hi, 2 lo) x 8 ntj paired:
//   base + (kidx*4 + ntj/2)*512 + lane*16 + (ntj&1)*8
// Biases: i,o rows pre-scaled by 0.5 (for sig via tanh); g rows plain.
__global__ void _LSTM_pack(const float* __restrict__ w_ih0,
                           const float* __restrict__ w_ih_rest,
                           const float* __restrict__ b_ih,
                           const float* __restrict__ b_hh,
                           const float* __restrict__ fc_w,
                           const float* __restrict__ fc_b) {
    int i = blockIdx.x * blockDim.x + threadIdx.x;
    if (i < 40960) {
        int s, q;
        if (i < 12288)       { s = 0; q = i; }
        else if (i < 36864)  { s = 1 + (i - 12288) / 6144; q = (i - 12288) % 6144; }
        else                 { s = 5; q = i - 36864; }
        int fid = q >> 7, r = q & 127;
        int lane = r >> 2, reg = (r >> 1) & 1, half = r & 1;
        int n = lane >> 2;
        int kel = (lane & 3) * 2 + half + reg * 8;
        float w; unsigned dst;
        if (s < 5) {
            const int KH = (s == 0) ? 4 : 2;
            const unsigned base =
                (s == 0) ? 0u : (unsigned)(24576 + (s - 1) * 12288);
            int kidx = fid / 12, nt = fid % 12;
            int gate = nt >> 2, ntj = nt & 3;
            int is_lo = kidx >= KH;
            int k = (is_lo ? kidx - KH : kidx) * 16 + kel;
            int j = gate * 32 + ntj * 8 + n;
            int rr = (j < 32) ? j : j + 32;
            if (s == 0) w = w_ih0[rr * 64 + k];
            else        w = w_ih_rest[(s - 1) * 4096 + rr * 32 + k];
            __half hi = __float2half_rn(w);
            __half v = is_lo ? __float2half_rn(w - __half2float(hi)) : hi;
            if (gate < 2)
                dst = base + (unsigned)(kidx * 4 + ntj) * 512
                    + lane * 16 + gate * 8 + reg * 4 + half * 2;
            else
                dst = base + (unsigned)KH * 4096 + (unsigned)(kidx * 4 + ntj) * 256
                    + lane * 8 + reg * 4 + half * 2;
            *(__half*)(g_img + dst) = v;
        } else {
            int kidx = fid / 8, nt = fid % 8;   // fid 0..31
            int is_lo = kidx >= 2;
            int k = (is_lo ? kidx - 2 : kidx) * 16 + kel;
            int j = nt * 8 + n;
            w = fc_w[j * 32 + k];
            __half hi = __float2half_rn(w);
            __half v = is_lo ? __float2half_rn(w - __half2float(hi)) : hi;
            dst = WB_FC + (unsigned)(kidx * 4 + (nt >> 1)) * 512
                + lane * 16 + (nt & 1) * 8 + reg * 4 + half * 2;
            *(__half*)(g_img + dst) = v;
        }
    } else if (i < 40960 + 544) {
        int b = i - 40960; float v;
        if (b < 480) {
            int l = b / 96, j = b % 96;
            int rr = (j < 32) ? j : j + 32;
            v = b_ih[l * 128 + rr] + b_hh[l * 128 + rr];
            if (j < 32 || j >= 64) v *= 0.5f;   // i,o rows: sig via tanh(x/2)
        } else v = fc_b[b - 480];
        *(float*)(g_img + BIAS_OFF + b * 4) = v;
    }
}

// -------- epilogue for one ntj group (8 cols x 2 m-tiles) --------
__device__ __forceinline__ void epi_ntj(
    const float (*Cp)[4],                  // [gate*2+m][q] accumulators
    const float* __restrict__ biasK, unsigned char* __restrict__ Abuf,
    int ntj, int g, int q4)
{
    const int col = ntj * 8 + q4 * 2;
    const float bi0 = biasK[col],      bi1 = biasK[col + 1];
    const float bg0 = biasK[32 + col], bg1 = biasK[33 + col];
    const float bo0 = biasK[64 + col], bo1 = biasK[65 + col];
#pragma unroll
    for (int m = 0; m < 2; m++) {
        float h0 = act_h(Cp[m][0], Cp[2 + m][0], Cp[4 + m][0], bi0, bg0, bo0);
        float h1 = act_h(Cp[m][1], Cp[2 + m][1], Cp[4 + m][1], bi1, bg1, bo1);
        float h2 = act_h(Cp[m][2], Cp[2 + m][2], Cp[4 + m][2], bi0, bg0, bo0);
        float h3 = act_h(Cp[m][3], Cp[2 + m][3], Cp[4 + m][3], bi1, bg1, bo1);
        unsigned char* r0 = Abuf + (m * 16 + g) * AP + 4 * (ntj * 4 + q4);
        *(uint32_t*)r0            = packh2(h0, h1);
        *(uint32_t*)(r0 + 8 * AP) = packh2(h2, h3);
    }
}

// -------- one 96-col LSTM layer, UNPIPELINED (used for L0, KH=4) --------
template<int KH>
__device__ __forceinline__ void layer96(
    const unsigned char* __restrict__ wimg, uint32_t wbase,
    const float* __restrict__ biasK, unsigned char* __restrict__ Abuf,
    int lane)
{
    const int g = lane >> 2, q4 = lane & 3;
    uint32_t Ah[2][KH][4];
#pragma unroll
    for (int m = 0; m < 2; m++)
#pragma unroll
        for (int tk = 0; tk < KH; tk++) {
            const unsigned char* ab =
                Abuf + (m * 16 + g) * AP + 32 * tk + 4 * q4;
            Ah[m][tk][0] = *(const uint32_t*)ab;
            Ah[m][tk][1] = *(const uint32_t*)(ab + 8 * AP);
            Ah[m][tk][2] = *(const uint32_t*)(ab + 16);
            Ah[m][tk][3] = *(const uint32_t*)(ab + 8 * AP + 16);
        }
    __syncwarp();

    const unsigned char* wIG = wimg + wbase + lane * 16;
    const unsigned char* wO  = wimg + wbase + KH * 4096 + lane * 8;

#pragma unroll
    for (int ntj = 0; ntj < 4; ntj++) {
        const unsigned char* aIG = wIG + ntj * 512;
        const unsigned char* aO  = wO  + ntj * 256;
        float C[6][4];
#pragma unroll
        for (int ch = 0; ch < 6; ch++)
#pragma unroll
            for (int q = 0; q < 4; q++) C[ch][q] = 0.f;
#pragma unroll
        for (int t = 0; t < 2 * KH; t++) {       // kidx = t (W hi then W lo)
            const int tk = t & (KH - 1);         // A reused for both segments
            uint4 igf = *(const uint4*)(aIG + t * 2048);
            uint2 of  = *(const uint2*)(aO  + t * 1024);
#pragma unroll
            for (int m = 0; m < 2; m++) {
                mma_f16(C[m],     Ah[m][tk], igf.x, igf.y);
                mma_f16(C[2 + m], Ah[m][tk], igf.z, igf.w);
                mma_f16(C[4 + m], Ah[m][tk], of.x,  of.y);
            }
        }
        epi_ntj(C, biasK, Abuf, ntj, g, q4);
    }
    __syncwarp();
}

// -------- one 96-col LSTM layer, PIPELINED (KH=2; L1..L4) --------
// 5-phase loop: MMA(ntj p) co-scheduled with EPI(p-1), double-buffered C.
__device__ __forceinline__ void layer96_piped(
    const unsigned char* __restrict__ wimg, uint32_t wbase,
    const float* __restrict__ biasK, unsigned char* __restrict__ Abuf,
    int lane)
{
    const int g = lane >> 2, q4 = lane & 3;
    uint32_t Ah[2][2][4];
#pragma unroll
    for (int m = 0; m < 2; m++)
#pragma unroll
        for (int tk = 0; tk < 2; tk++) {
            const unsigned char* ab =
                Abuf + (m * 16 + g) * AP + 32 * tk + 4 * q4;
            Ah[m][tk][0] = *(const uint32_t*)ab;
            Ah[m][tk][1] = *(const uint32_t*)(ab + 8 * AP);
            Ah[m][tk][2] = *(const uint32_t*)(ab + 16);
            Ah[m][tk][3] = *(const uint32_t*)(ab + 8 * AP + 16);
        }
    __syncwarp();

    const unsigned char* wIG = wimg + wbase + lane * 16;
    const unsigned char* wO  = wimg + wbase + 2 * 4096 + lane * 8;

    float C[2][6][4];   // [buf][gate*2+m][q]

#pragma unroll
    for (int p = 0; p < 5; p++) {
        if (p < 4) {
            float (*Cc)[4] = C[p & 1];
#pragma unroll
            for (int ch = 0; ch < 6; ch++)
#pragma unroll
                for (int q = 0; q < 4; q++) Cc[ch][q] = 0.f;
            const unsigned char* aIG = wIG + p * 512;
            const unsigned char* aO  = wO  + p * 256;
#pragma unroll
            for (int t = 0; t < 4; t++) {        // kidx = t (2 hi, 2 lo)
                const int tk = t & 1;
                uint4 igf = *(const uint4*)(aIG + t * 2048);
                uint2 of  = *(const uint2*)(aO  + t * 1024);
#pragma unroll
                for (int m = 0; m < 2; m++) {
                    mma_f16(Cc[m],     Ah[m][tk], igf.x, igf.y);
                    mma_f16(Cc[2 + m], Ah[m][tk], igf.z, igf.w);
                    mma_f16(Cc[4 + m], Ah[m][tk], of.x,  of.y);
                }
            }
        }
        if (p > 0)
            epi_ntj(C[(p - 1) & 1], biasK, Abuf, p - 1, g, q4);
    }
    __syncwarp();
}

// -------- fc: A in regs; paired-ntj LDS.128 weights; f32 out staged --------
__device__ __forceinline__ void fc_stage(
    const unsigned char* __restrict__ wimg,
    const float* __restrict__ fb, unsigned char* __restrict__ Abuf, int lane)
{
    const int g = lane >> 2, q4 = lane & 3;
    uint32_t Ah[2][2][4];
#pragma unroll
    for (int m = 0; m < 2; m++)
#pragma unroll
        for (int tk = 0; tk < 2; tk++) {
            const unsigned char* ab =
                Abuf + (m * 16 + g) * AP + 32 * tk + 4 * q4;
            Ah[m][tk][0] = *(const uint32_t*)ab;
            Ah[m][tk][1] = *(const uint32_t*)(ab + 8 * AP);
            Ah[m][tk][2] = *(const uint32_t*)(ab + 16);
            Ah[m][tk][3] = *(const uint32_t*)(ab + 8 * AP + 16);
        }
    __syncwarp();

    const unsigned char* wp = wimg + WB_FC + lane * 16;

#pragma unroll
    for (int np = 0; np < 4; np++) {           // ntj pairs (2np, 2np+1)
        float C0[2][4], C1[2][4];
#pragma unroll
        for (int m = 0; m < 2; m++)
#pragma unroll
            for (int q = 0; q < 4; q++) { C0[m][q] = 0.f; C1[m][q] = 0.f; }
#pragma unroll
        for (int t = 0; t < 4; t++) {          // kidx = t (2 hi, 2 lo)
            const int tk = t & 1;
            uint4 bf = *(const uint4*)(wp + (uint32_t)(t * 4 + np) * 512);
#pragma unroll
            for (int m = 0; m < 2; m++) {
                mma_f16(C0[m], Ah[m][tk], bf.x, bf.y);
                mma_f16(C1[m], Ah[m][tk], bf.z, bf.w);
            }
        }
#pragma unroll
        for (int half = 0; half < 2; half++) {
            float (*C)[4] = half ? C1 : C0;
            const int col = (np * 2 + half) * 8 + q4 * 2;
            const float b0 = fb[col], b1 = fb[col + 1];
#pragma unroll
            for (int m = 0; m < 2; m++) {
                float* r0 = (float*)(Abuf + (m * 16 + g) * AP + 4 * col);
                float* r1 = (float*)((unsigned char*)r0 + 8 * AP);
                r0[0] = C[m][0] + b0; r0[1] = C[m][1] + b1;
                r1[0] = C[m][2] + b0; r1[1] = C[m][3] + b1;
            }
        }
    }
    __syncwarp();
}

// ---------------- main persistent kernel ----------------
__global__ void __launch_bounds__(NT, 1)
_LSTM_main(const float* __restrict__ x, float* __restrict__ out, int B) {
    extern __shared__ unsigned char smem[];
    const int tid = threadIdx.x;
    const int wid = tid >> 5;
    const int lane = tid & 31;

#pragma unroll 4
    for (int p = tid; p < WIMG / 16; p += NT)
        ((uint4*)smem)[p] = ((const uint4*)g_img)[p];
    __syncthreads();

    unsigned char* Abuf = smem + WIMG + wid * WARP_ABUF;
    const float* biasK = (const float*)(smem + BIAS_OFF);
    const float4* x4 = (const float4*)x;
    float4* o4 = (float4*)out;

    const int npair = (B + 511) >> 9;

#pragma unroll 1
    for (int it = blockIdx.x; it < npair; it += GRID) {
        const long long rowbase = (long long)it * 512 + wid * 32;

        // ---- load 32 x-rows, convert to fp16, stage (row = 128B) ----
#pragma unroll
        for (int i = 0; i < 16; i++) {
            int p = lane + i * 32;
            int r = p >> 4, c4 = p & 15;
            long long grow = rowbase + r;
            float4 v = (grow < B) ? x4[grow * 16 + c4]
                                  : make_float4(0.f, 0.f, 0.f, 0.f);
            uint32_t h0 = packh2(v.x, v.y), h1 = packh2(v.z, v.w);
            *(uint2*)(Abuf + r * AP + 8 * c4) = make_uint2(h0, h1);
        }
        __syncwarp();

        // ---- 5 LSTM layers (in-place, A in regs) + fc ----
        layer96<4>(smem, WB_L0, biasK, Abuf, lane);
        layer96_piped(smem, WB_L1, biasK + 96,  Abuf, lane);
        layer96_piped(smem, WB_L2, biasK + 192, Abuf, lane);
        layer96_piped(smem, WB_L3, biasK + 288, Abuf, lane);
        layer96_piped(smem, WB_L4, biasK + 384, Abuf, lane);
        fc_stage(smem, biasK + 480, Abuf, lane);

        // ---- coalesced f32 store ----
#pragma unroll
        for (int i = 0; i < 16; i++) {
            int p = lane + i * 32;
            int r = p >> 4, c4 = p & 15;
            long long grow = rowbase + r;
            if (grow < B)
                o4[grow * 16 + c4] = *(const float4*)(Abuf + r * AP + 16 * c4);
        }
        __syncwarp();
    }
}

// ---------------- launch ----------------
extern "C" void kernel_launch(void* const* d_in, const int* in_sizes, int n_in,
                              void* d_out, int out_size) {
    (void)n_in; (void)out_size;
    const float* x         = (const float*)d_in[0];
    const float* w_ih0     = (const float*)d_in[1];
    // d_in[2] = w_hh0      (unused: h0 == 0, T == 1)
    const float* w_ih_rest = (const float*)d_in[3];
    // d_in[4] = w_hh_rest  (unused)
    const float* b_ih      = (const float*)d_in[5];
    const float* b_hh      = (const float*)d_in[6];
    const float* fc_w      = (const float*)d_in[7];
    const float* fc_b      = (const float*)d_in[8];
    float* out = (float*)d_out;

    int B = in_sizes[0] / 64;

    _LSTM_pack<<<(40960 + 544 + 255) / 256, 256>>>(
        w_ih0, w_ih_rest, b_ih, b_hh, fc_w, fc_b);

    cudaFuncSetAttribute(_LSTM_main,
                         cudaFuncAttributeMaxDynamicSharedMemorySize, SMEM_BYTES);
    int npair = (B + 511) / 512;
    int grid = npair < GRID ? npair : GRID;
    _LSTM_main<<<grid, NT, SMEM_BYTES>>>(x, out, B);
}

// round 13
// speedup vs baseline: 1.2801x; 1.2801x over previous
#include <cuda_runtime.h>
#include <cuda_fp16.h>
#include <cstdint>

// ============================================================================
// T=1, h0=c0=0 => w_hh* unused, f-gate unused. Chain of small GEMMs on HMMA
// (mma.sync m16n8k16 fp16 -> f32 accum).
// R13 precision: PLAIN fp16 for both A and W (single MMA pass).
//   Gate err ~3.4e-4 std; measured transfer (R10: 2.3e-4 -> 4.2e-5 final)
//   predicts final rel_err ~6e-5, 15x under the 1e-3 gate.
//   Halves the tensor floor (320 MMA/warp/iter) and weight-LDS traffic.
// R11 epilogue (kept): sig via tanh.approx.f32 => 4 MUFU + ~7 FMA per h.
// Persistent: 148 CTAs x 512 thr; warp owns 32 rows, warp-private A smem.
// ============================================================================

#define NT    512
#define GRID  148
#define AP    272
#define WIMG  43136                      // 40960B weights + 544*4B biases
#define WARP_ABUF (32 * AP)
#define SMEM_BYTES (WIMG + 16 * WARP_ABUF)

// stage bases (bytes); per LSTM stage: [IG groups (KH*2048)][O frags (KH*1024)]
#define WB_L0 0
#define WB_L1 12288
#define WB_L2 18432
#define WB_L3 24576
#define WB_L4 30720
#define WB_FC 36864
#define BIAS_OFF 40960

__device__ __align__(16) unsigned char g_img[WIMG];

// ---------------- fast math ----------------
__device__ __forceinline__ float tanhap(float x) {
    float y; asm("tanh.approx.f32 %0, %1;" : "=f"(y) : "f"(x)); return y;
}
__device__ __forceinline__ uint32_t packh2(float a, float b) {
    __half2 v = __float22half2_rn(make_float2(a, b));
    return *reinterpret_cast<uint32_t*>(&v);
}

// fused LSTM activation: h = sig(o)*tanh(sig(i)*tanh(g)).
// bi,bo arrive pre-scaled by 0.5; bg plain.
__device__ __forceinline__ float act_h(float ci, float cg, float co,
                                       float bi, float bg, float bo) {
    float si = fmaf(tanhap(fmaf(ci, 0.5f, bi)), 0.5f, 0.5f);
    float tg = tanhap(cg + bg);
    float tc = tanhap(si * tg);
    float so = fmaf(tanhap(fmaf(co, 0.5f, bo)), 0.5f, 0.5f);
    return so * tc;
}

// ---------------- mma (fp16 inputs, f32 accum) ----------------
__device__ __forceinline__ void mma_f16(float c[4],
    const uint32_t a[4], uint32_t b0, uint32_t b1) {
    asm volatile(
        "mma.sync.aligned.m16n8k16.row.col.f32.f16.f16.f32 "
        "{%0,%1,%2,%3},{%4,%5,%6,%7},{%8,%9},{%0,%1,%2,%3};"
        : "+f"(c[0]), "+f"(c[1]), "+f"(c[2]), "+f"(c[3])
        : "r"(a[0]), "r"(a[1]), "r"(a[2]), "r"(a[3]), "r"(b0), "r"(b1));
}

// ---------------- weight pack: v2 layout, plain fp16 ----------------
// LSTM stage s (KH = 4 for L0 else 2): kidx 0..KH-1 x 4 ntj.
//   IG group (kidx,ntj) at base + (kidx*4+ntj)*512: per lane 16B = i0,i1,g0,g1
//   O frag at base + KH*2048 + (kidx*4+ntj)*256: per lane 8B = o0,o1
// FC: kidx 0..1 x 8 ntj paired:
//   WB_FC + (kidx*4 + ntj/2)*512 + lane*16 + (ntj&1)*8
// Biases: i,o rows pre-scaled by 0.5 (sig via tanh); g rows plain.
__global__ void _LSTM_pack(const float* __restrict__ w_ih0,
                           const float* __restrict__ w_ih_rest,
                           const float* __restrict__ b_ih,
                           const float* __restrict__ b_hh,
                           const float* __restrict__ fc_w,
                           const float* __restrict__ fc_b) {
    int i = blockIdx.x * blockDim.x + threadIdx.x;
    if (i < 20480) {
        int s, q;
        if (i < 6144)        { s = 0; q = i; }
        else if (i < 18432)  { s = 1 + (i - 6144) / 3072; q = (i - 6144) % 3072; }
        else                 { s = 5; q = i - 18432; }
        int fid = q >> 7, r = q & 127;
        int lane = r >> 2, reg = (r >> 1) & 1, half = r & 1;
        int n = lane >> 2;
        int kel = (lane & 3) * 2 + half + reg * 8;
        float w; unsigned dst;
        if (s < 5) {
            const int KH = (s == 0) ? 4 : 2;
            const unsigned base =
                (s == 0) ? 0u : (unsigned)(12288 + (s - 1) * 6144);
            int kidx = fid / 12, nt = fid % 12;
            int gate = nt >> 2, ntj = nt & 3;
            int k = kidx * 16 + kel;
            int j = gate * 32 + ntj * 8 + n;
            int rr = (j < 32) ? j : j + 32;
            if (s == 0) w = w_ih0[rr * 64 + k];
            else        w = w_ih_rest[(s - 1) * 4096 + rr * 32 + k];
            if (gate < 2)
                dst = base + (unsigned)(kidx * 4 + ntj) * 512
                    + lane * 16 + gate * 8 + reg * 4 + half * 2;
            else
                dst = base + (unsigned)KH * 2048 + (unsigned)(kidx * 4 + ntj) * 256
                    + lane * 8 + reg * 4 + half * 2;
            *(__half*)(g_img + dst) = __float2half_rn(w);
        } else {
            int kidx = fid / 8, nt = fid % 8;   // fid 0..15
            int k = kidx * 16 + kel;
            int j = nt * 8 + n;
            w = fc_w[j * 32 + k];
            dst = WB_FC + (unsigned)(kidx * 4 + (nt >> 1)) * 512
                + lane * 16 + (nt & 1) * 8 + reg * 4 + half * 2;
            *(__half*)(g_img + dst) = __float2half_rn(w);
        }
    } else if (i < 20480 + 544) {
        int b = i - 20480; float v;
        if (b < 480) {
            int l = b / 96, j = b % 96;
            int rr = (j < 32) ? j : j + 32;
            v = b_ih[l * 128 + rr] + b_hh[l * 128 + rr];
            if (j < 32 || j >= 64) v *= 0.5f;   // i,o rows: sig via tanh(x/2)
        } else v = fc_b[b - 480];
        *(float*)(g_img + BIAS_OFF + b * 4) = v;
    }
}

// -------- one 96-col LSTM layer: A fully in regs, in-place h --------
template<int KH>
__device__ __forceinline__ void layer96(
    const unsigned char* __restrict__ wimg, uint32_t wbase,
    const float* __restrict__ biasK, unsigned char* __restrict__ Abuf,
    int lane)
{
    const int g = lane >> 2, q4 = lane & 3;
    uint32_t Ah[2][KH][4];
#pragma unroll
    for (int m = 0; m < 2; m++)
#pragma unroll
        for (int tk = 0; tk < KH; tk++) {
            const unsigned char* ab =
                Abuf + (m * 16 + g) * AP + 32 * tk + 4 * q4;
            Ah[m][tk][0] = *(const uint32_t*)ab;
            Ah[m][tk][1] = *(const uint32_t*)(ab + 8 * AP);
            Ah[m][tk][2] = *(const uint32_t*)(ab + 16);
            Ah[m][tk][3] = *(const uint32_t*)(ab + 8 * AP + 16);
        }
    __syncwarp();   // all lanes' A in regs before any h writes below

    const unsigned char* wIG = wimg + wbase + lane * 16;
    const unsigned char* wO  = wimg + wbase + KH * 2048 + lane * 8;

#pragma unroll
    for (int ntj = 0; ntj < 4; ntj++) {
        const unsigned char* aIG = wIG + ntj * 512;
        const unsigned char* aO  = wO  + ntj * 256;
        float Ci[2][4], Cg[2][4], Co[2][4];
#pragma unroll
        for (int m = 0; m < 2; m++)
#pragma unroll
            for (int q = 0; q < 4; q++) {
                Ci[m][q] = 0.f; Cg[m][q] = 0.f; Co[m][q] = 0.f;
            }
#pragma unroll
        for (int t = 0; t < KH; t++) {
            uint4 igf = *(const uint4*)(aIG + t * 2048);
            uint2 of  = *(const uint2*)(aO  + t * 1024);
#pragma unroll
            for (int m = 0; m < 2; m++) {
                mma_f16(Ci[m], Ah[m][t], igf.x, igf.y);
                mma_f16(Cg[m], Ah[m][t], igf.z, igf.w);
                mma_f16(Co[m], Ah[m][t], of.x,  of.y);
            }
        }
        const int col = ntj * 8 + q4 * 2;
        const float bi0 = biasK[col],      bi1 = biasK[col + 1];
        const float bg0 = biasK[32 + col], bg1 = biasK[33 + col];
        const float bo0 = biasK[64 + col], bo1 = biasK[65 + col];
#pragma unroll
        for (int m = 0; m < 2; m++) {
            float h0 = act_h(Ci[m][0], Cg[m][0], Co[m][0], bi0, bg0, bo0);
            float h1 = act_h(Ci[m][1], Cg[m][1], Co[m][1], bi1, bg1, bo1);
            float h2 = act_h(Ci[m][2], Cg[m][2], Co[m][2], bi0, bg0, bo0);
            float h3 = act_h(Ci[m][3], Cg[m][3], Co[m][3], bi1, bg1, bo1);
            unsigned char* r0 =
                Abuf + (m * 16 + g) * AP + 4 * (ntj * 4 + q4);
            *(uint32_t*)r0            = packh2(h0, h1);
            *(uint32_t*)(r0 + 8 * AP) = packh2(h2, h3);
        }
    }
    __syncwarp();
}

// -------- fc: A in regs; paired-ntj LDS.128 weights; f32 out staged --------
__device__ __forceinline__ void fc_stage(
    const unsigned char* __restrict__ wimg,
    const float* __restrict__ fb, unsigned char* __restrict__ Abuf, int lane)
{
    const int g = lane >> 2, q4 = lane & 3;
    uint32_t Ah[2][2][4];
#pragma unroll
    for (int m = 0; m < 2; m++)
#pragma unroll
        for (int tk = 0; tk < 2; tk++) {
            const unsigned char* ab =
                Abuf + (m * 16 + g) * AP + 32 * tk + 4 * q4;
            Ah[m][tk][0] = *(const uint32_t*)ab;
            Ah[m][tk][1] = *(const uint32_t*)(ab + 8 * AP);
            Ah[m][tk][2] = *(const uint32_t*)(ab + 16);
            Ah[m][tk][3] = *(const uint32_t*)(ab + 8 * AP + 16);
        }
    __syncwarp();

    const unsigned char* wp = wimg + WB_FC + lane * 16;

#pragma unroll
    for (int np = 0; np < 4; np++) {           // ntj pairs (2np, 2np+1)
        float C0[2][4], C1[2][4];
#pragma unroll
        for (int m = 0; m < 2; m++)
#pragma unroll
            for (int q = 0; q < 4; q++) { C0[m][q] = 0.f; C1[m][q] = 0.f; }
#pragma unroll
        for (int t = 0; t < 2; t++) {
            uint4 bf = *(const uint4*)(wp + (uint32_t)(t * 4 + np) * 512);
#pragma unroll
            for (int m = 0; m < 2; m++) {
                mma_f16(C0[m], Ah[m][t], bf.x, bf.y);
                mma_f16(C1[m], Ah[m][t], bf.z, bf.w);
            }
        }
#pragma unroll
        for (int half = 0; half < 2; half++) {
            float (*C)[4] = half ? C1 : C0;
            const int col = (np * 2 + half) * 8 + q4 * 2;
            const float b0 = fb[col], b1 = fb[col + 1];
#pragma unroll
            for (int m = 0; m < 2; m++) {
                float* r0 = (float*)(Abuf + (m * 16 + g) * AP + 4 * col);
                float* r1 = (float*)((unsigned char*)r0 + 8 * AP);
                r0[0] = C[m][0] + b0; r0[1] = C[m][1] + b1;
                r1[0] = C[m][2] + b0; r1[1] = C[m][3] + b1;
            }
        }
    }
    __syncwarp();
}

// ---------------- main persistent kernel ----------------
__global__ void __launch_bounds__(NT, 1)
_LSTM_main(const float* __restrict__ x, float* __restrict__ out, int B) {
    extern __shared__ unsigned char smem[];
    const int tid = threadIdx.x;
    const int wid = tid >> 5;
    const int lane = tid & 31;

#pragma unroll 4
    for (int p = tid; p < WIMG / 16; p += NT)
        ((uint4*)smem)[p] = ((const uint4*)g_img)[p];
    __syncthreads();

    unsigned char* Abuf = smem + WIMG + wid * WARP_ABUF;
    const float* biasK = (const float*)(smem + BIAS_OFF);
    const float4* x4 = (const float4*)x;
    float4* o4 = (float4*)out;

    const int npair = (B + 511) >> 9;

#pragma unroll 1
    for (int it = blockIdx.x; it < npair; it += GRID) {
        const long long rowbase = (long long)it * 512 + wid * 32;

        // ---- load 32 x-rows, convert to fp16, stage (row = 128B) ----
#pragma unroll
        for (int i = 0; i < 16; i++) {
            int p = lane + i * 32;
            int r = p >> 4, c4 = p & 15;
            long long grow = rowbase + r;
            float4 v = (grow < B) ? x4[grow * 16 + c4]
                                  : make_float4(0.f, 0.f, 0.f, 0.f);
            uint32_t h0 = packh2(v.x, v.y), h1 = packh2(v.z, v.w);
            *(uint2*)(Abuf + r * AP + 8 * c4) = make_uint2(h0, h1);
        }
        __syncwarp();

        // ---- 5 LSTM layers (in-place, A in regs) + fc ----
        layer96<4>(smem, WB_L0, biasK,       Abuf, lane);
        layer96<2>(smem, WB_L1, biasK + 96,  Abuf, lane);
        layer96<2>(smem, WB_L2, biasK + 192, Abuf, lane);
        layer96<2>(smem, WB_L3, biasK + 288, Abuf, lane);
        layer96<2>(smem, WB_L4, biasK + 384, Abuf, lane);
        fc_stage(smem, biasK + 480, Abuf, lane);

        // ---- coalesced f32 store ----
#pragma unroll
        for (int i = 0; i < 16; i++) {
            int p = lane + i * 32;
            int r = p >> 4, c4 = p & 15;
            long long grow = rowbase + r;
            if (grow < B)
                o4[grow * 16 + c4] = *(const float4*)(Abuf + r * AP + 16 * c4);
        }
        __syncwarp();
    }
}

// ---------------- launch ----------------
extern "C" void kernel_launch(void* const* d_in, const int* in_sizes, int n_in,
                              void* d_out, int out_size) {
    (void)n_in; (void)out_size;
    const float* x         = (const float*)d_in[0];
    const float* w_ih0     = (const float*)d_in[1];
    // d_in[2] = w_hh0      (unused: h0 == 0, T == 1)
    const float* w_ih_rest = (const float*)d_in[3];
    // d_in[4] = w_hh_rest  (unused)
    const float* b_ih      = (const float*)d_in[5];
    const float* b_hh      = (const float*)d_in[6];
    const float* fc_w      = (const float*)d_in[7];
    const float* fc_b      = (const float*)d_in[8];
    float* out = (float*)d_out;

    int B = in_sizes[0] / 64;

    _LSTM_pack<<<(20480 + 544 + 255) / 256, 256>>>(
        w_ih0, w_ih_rest, b_ih, b_hh, fc_w, fc_b);

    cudaFuncSetAttribute(_LSTM_main,
                         cudaFuncAttributeMaxDynamicSharedMemorySize, SMEM_BYTES);
    int npair = (B + 511) / 512;
    int grid = npair < GRID ? npair : GRID;
    _LSTM_main<<<grid, NT, SMEM_BYTES>>>(x, out, B);
}

// round 14
// speedup vs baseline: 1.3196x; 1.0309x over previous
#include <cuda_runtime.h>
#include <cuda_fp16.h>
#include <cstdint>

// ============================================================================
// T=1, h0=c0=0 => w_hh* unused, f-gate unused. Chain of small GEMMs on HMMA
// (mma.sync m16n8k16 fp16 -> f32 accum).
// R13 (kept): plain fp16 A and W, single MMA pass (gate err ~3.4e-4).
// R14: epilogue fully in fp16x2: tanh.approx.f16x2 + HFMA2/HMUL2.
//   sig(x)=0.5*tanh(x/2)+0.5 with biases pre-packed as half2 (i,o scaled 0.5).
//   MUFU instrs halve (4 f16x2 tanh per h-PAIR); h2 result stores directly.
//   h is already fp16 in smem, so fp16 epilogue error is comparable to the
//   existing quantization; predicted final rel_err ~2e-4 (measured transfer).
// Persistent: 148 CTAs x 512 thr; warp owns 32 rows, warp-private A smem.
// ============================================================================

#define NT    512
#define GRID  148
#define AP    272
#define WIMG  42176                  // 40960 weights + 960 half biases + 256 fc
#define WARP_ABUF (32 * AP)
#define SMEM_BYTES (WIMG + 16 * WARP_ABUF)

// stage bases (bytes); per LSTM stage: [IG groups (KH*2048)][O frags (KH*1024)]
#define WB_L0 0
#define WB_L1 12288
#define WB_L2 18432
#define WB_L3 24576
#define WB_L4 30720
#define WB_FC 36864
#define BIAS_OFF 40960               // 480 halfs: [layer][i(32)|g(32)|o(32)]
#define FCB_OFF  41920               // 64 f32 fc biases

__device__ __align__(16) unsigned char g_img[WIMG];

// ---------------- fast math ----------------
__device__ __forceinline__ uint32_t tanh2(uint32_t x) {
    uint32_t y; asm("tanh.approx.f16x2 %0, %1;" : "=r"(y) : "r"(x)); return y;
}
__device__ __forceinline__ uint32_t packh2(float a, float b) {
    __half2 v = __float22half2_rn(make_float2(a, b));
    return *reinterpret_cast<uint32_t*>(&v);
}
__device__ __forceinline__ __half2 as_h2(uint32_t v) {
    return *reinterpret_cast<__half2*>(&v);
}
__device__ __forceinline__ uint32_t as_u(__half2 v) {
    return *reinterpret_cast<uint32_t*>(&v);
}

// fused fp16x2 activation for an h-PAIR.
// bi2,bo2 pre-scaled by 0.5 (sig via tanh(x/2)); bg2 plain. Returns fp16x2 h.
__device__ __forceinline__ uint32_t act_h2(
    float ci0, float ci1, float cg0, float cg1, float co0, float co1,
    uint32_t bi2, uint32_t bg2, uint32_t bo2, __half2 H05)
{
    __half2 ui = __hfma2(as_h2(packh2(ci0, ci1)), H05, as_h2(bi2));
    __half2 si = __hfma2(as_h2(tanh2(as_u(ui))), H05, H05);
    __half2 ug = __hadd2(as_h2(packh2(cg0, cg1)), as_h2(bg2));
    __half2 c2 = __hmul2(si, as_h2(tanh2(as_u(ug))));
    uint32_t tc = tanh2(as_u(c2));
    __half2 uo = __hfma2(as_h2(packh2(co0, co1)), H05, as_h2(bo2));
    __half2 so = __hfma2(as_h2(tanh2(as_u(uo))), H05, H05);
    return as_u(__hmul2(so, as_h2(tc)));
}

// ---------------- mma (fp16 inputs, f32 accum) ----------------
__device__ __forceinline__ void mma_f16(float c[4],
    const uint32_t a[4], uint32_t b0, uint32_t b1) {
    asm volatile(
        "mma.sync.aligned.m16n8k16.row.col.f32.f16.f16.f32 "
        "{%0,%1,%2,%3},{%4,%5,%6,%7},{%8,%9},{%0,%1,%2,%3};"
        : "+f"(c[0]), "+f"(c[1]), "+f"(c[2]), "+f"(c[3])
        : "r"(a[0]), "r"(a[1]), "r"(a[2]), "r"(a[3]), "r"(b0), "r"(b1));
}

// ---------------- weight pack: v2 layout, plain fp16 (R13) ----------------
// LSTM stage s (KH = 4 for L0 else 2): kidx 0..KH-1 x 4 ntj.
//   IG group (kidx,ntj) at base + (kidx*4+ntj)*512: per lane 16B = i0,i1,g0,g1
//   O frag at base + KH*2048 + (kidx*4+ntj)*256: per lane 8B = o0,o1
// FC: kidx 0..1 x 8 ntj paired.
// Biases: half at BIAS_OFF (layer stride 192B: i,g,o 64B each);
//   i,o pre-scaled 0.5. fc f32 at FCB_OFF.
__global__ void _LSTM_pack(const float* __restrict__ w_ih0,
                           const float* __restrict__ w_ih_rest,
                           const float* __restrict__ b_ih,
                           const float* __restrict__ b_hh,
                           const float* __restrict__ fc_w,
                           const float* __restrict__ fc_b) {
    int i = blockIdx.x * blockDim.x + threadIdx.x;
    if (i < 20480) {
        int s, q;
        if (i < 6144)        { s = 0; q = i; }
        else if (i < 18432)  { s = 1 + (i - 6144) / 3072; q = (i - 6144) % 3072; }
        else                 { s = 5; q = i - 18432; }
        int fid = q >> 7, r = q & 127;
        int lane = r >> 2, reg = (r >> 1) & 1, half = r & 1;
        int n = lane >> 2;
        int kel = (lane & 3) * 2 + half + reg * 8;
        float w; unsigned dst;
        if (s < 5) {
            const int KH = (s == 0) ? 4 : 2;
            const unsigned base =
                (s == 0) ? 0u : (unsigned)(12288 + (s - 1) * 6144);
            int kidx = fid / 12, nt = fid % 12;
            int gate = nt >> 2, ntj = nt & 3;
            int k = kidx * 16 + kel;
            int j = gate * 32 + ntj * 8 + n;
            int rr = (j < 32) ? j : j + 32;
            if (s == 0) w = w_ih0[rr * 64 + k];
            else        w = w_ih_rest[(s - 1) * 4096 + rr * 32 + k];
            if (gate < 2)
                dst = base + (unsigned)(kidx * 4 + ntj) * 512
                    + lane * 16 + gate * 8 + reg * 4 + half * 2;
            else
                dst = base + (unsigned)KH * 2048 + (unsigned)(kidx * 4 + ntj) * 256
                    + lane * 8 + reg * 4 + half * 2;
            *(__half*)(g_img + dst) = __float2half_rn(w);
        } else {
            int kidx = fid / 8, nt = fid % 8;   // fid 0..15
            int k = kidx * 16 + kel;
            int j = nt * 8 + n;
            w = fc_w[j * 32 + k];
            dst = WB_FC + (unsigned)(kidx * 4 + (nt >> 1)) * 512
                + lane * 16 + (nt & 1) * 8 + reg * 4 + half * 2;
            *(__half*)(g_img + dst) = __float2half_rn(w);
        }
    } else if (i < 20480 + 480) {
        int b = i - 20480;                  // LSTM biases -> half
        int l = b / 96, j = b % 96;
        int rr = (j < 32) ? j : j + 32;
        float v = b_ih[l * 128 + rr] + b_hh[l * 128 + rr];
        if (j < 32 || j >= 64) v *= 0.5f;   // i,o rows: sig via tanh(x/2)
        *(__half*)(g_img + BIAS_OFF + b * 2) = __float2half_rn(v);
    } else if (i < 20480 + 480 + 64) {
        int b = i - 20480 - 480;            // fc biases -> f32
        *(float*)(g_img + FCB_OFF + b * 4) = fc_b[b];
    }
}

// -------- one 96-col LSTM layer: A fully in regs, in-place h --------
// biasB points at this layer's half-bias block (i at +0, g at +64, o at +128).
template<int KH>
__device__ __forceinline__ void layer96(
    const unsigned char* __restrict__ wimg, uint32_t wbase,
    const unsigned char* __restrict__ biasB, unsigned char* __restrict__ Abuf,
    int lane, __half2 H05)
{
    const int g = lane >> 2, q4 = lane & 3;
    uint32_t Ah[2][KH][4];
#pragma unroll
    for (int m = 0; m < 2; m++)
#pragma unroll
        for (int tk = 0; tk < KH; tk++) {
            const unsigned char* ab =
                Abuf + (m * 16 + g) * AP + 32 * tk + 4 * q4;
            Ah[m][tk][0] = *(const uint32_t*)ab;
            Ah[m][tk][1] = *(const uint32_t*)(ab + 8 * AP);
            Ah[m][tk][2] = *(const uint32_t*)(ab + 16);
            Ah[m][tk][3] = *(const uint32_t*)(ab + 8 * AP + 16);
        }
    __syncwarp();   // all lanes' A in regs before any h writes below

    const unsigned char* wIG = wimg + wbase + lane * 16;
    const unsigned char* wO  = wimg + wbase + KH * 2048 + lane * 8;

#pragma unroll
    for (int ntj = 0; ntj < 4; ntj++) {
        const unsigned char* aIG = wIG + ntj * 512;
        const unsigned char* aO  = wO  + ntj * 256;
        float Ci[2][4], Cg[2][4], Co[2][4];
#pragma unroll
        for (int m = 0; m < 2; m++)
#pragma unroll
            for (int q = 0; q < 4; q++) {
                Ci[m][q] = 0.f; Cg[m][q] = 0.f; Co[m][q] = 0.f;
            }
#pragma unroll
        for (int t = 0; t < KH; t++) {
            uint4 igf = *(const uint4*)(aIG + t * 2048);
            uint2 of  = *(const uint2*)(aO  + t * 1024);
#pragma unroll
            for (int m = 0; m < 2; m++) {
                mma_f16(Ci[m], Ah[m][t], igf.x, igf.y);
                mma_f16(Cg[m], Ah[m][t], igf.z, igf.w);
                mma_f16(Co[m], Ah[m][t], of.x,  of.y);
            }
        }
        const int col = ntj * 8 + q4 * 2;
        const uint32_t bi2 = *(const uint32_t*)(biasB + col * 2);
        const uint32_t bg2 = *(const uint32_t*)(biasB + 64 + col * 2);
        const uint32_t bo2 = *(const uint32_t*)(biasB + 128 + col * 2);
#pragma unroll
        for (int m = 0; m < 2; m++) {
            unsigned char* r0 =
                Abuf + (m * 16 + g) * AP + 4 * (ntj * 4 + q4);
            *(uint32_t*)r0 =
                act_h2(Ci[m][0], Ci[m][1], Cg[m][0], Cg[m][1],
                       Co[m][0], Co[m][1], bi2, bg2, bo2, H05);
            *(uint32_t*)(r0 + 8 * AP) =
                act_h2(Ci[m][2], Ci[m][3], Cg[m][2], Cg[m][3],
                       Co[m][2], Co[m][3], bi2, bg2, bo2, H05);
        }
    }
    __syncwarp();
}

// -------- fc: A in regs; paired-ntj LDS.128 weights; f32 out staged --------
__device__ __forceinline__ void fc_stage(
    const unsigned char* __restrict__ wimg,
    const float* __restrict__ fb, unsigned char* __restrict__ Abuf, int lane)
{
    const int g = lane >> 2, q4 = lane & 3;
    uint32_t Ah[2][2][4];
#pragma unroll
    for (int m = 0; m < 2; m++)
#pragma unroll
        for (int tk = 0; tk < 2; tk++) {
            const unsigned char* ab =
                Abuf + (m * 16 + g) * AP + 32 * tk + 4 * q4;
            Ah[m][tk][0] = *(const uint32_t*)ab;
            Ah[m][tk][1] = *(const uint32_t*)(ab + 8 * AP);
            Ah[m][tk][2] = *(const uint32_t*)(ab + 16);
            Ah[m][tk][3] = *(const uint32_t*)(ab + 8 * AP + 16);
        }
    __syncwarp();

    const unsigned char* wp = wimg + WB_FC + lane * 16;

#pragma unroll
    for (int np = 0; np < 4; np++) {           // ntj pairs (2np, 2np+1)
        float C0[2][4], C1[2][4];
#pragma unroll
        for (int m = 0; m < 2; m++)
#pragma unroll
            for (int q = 0; q < 4; q++) { C0[m][q] = 0.f; C1[m][q] = 0.f; }
#pragma unroll
        for (int t = 0; t < 2; t++) {
            uint4 bf = *(const uint4*)(wp + (uint32_t)(t * 4 + np) * 512);
#pragma unroll
            for (int m = 0; m < 2; m++) {
                mma_f16(C0[m], Ah[m][t], bf.x, bf.y);
                mma_f16(C1[m], Ah[m][t], bf.z, bf.w);
            }
        }
#pragma unroll
        for (int half = 0; half < 2; half++) {
            float (*C)[4] = half ? C1 : C0;
            const int col = (np * 2 + half) * 8 + q4 * 2;
            const float b0 = fb[col], b1 = fb[col + 1];
#pragma unroll
            for (int m = 0; m < 2; m++) {
                float* r0 = (float*)(Abuf + (m * 16 + g) * AP + 4 * col);
                float* r1 = (float*)((unsigned char*)r0 + 8 * AP);
                r0[0] = C[m][0] + b0; r0[1] = C[m][1] + b1;
                r1[0] = C[m][2] + b0; r1[1] = C[m][3] + b1;
            }
        }
    }
    __syncwarp();
}

// ---------------- main persistent kernel ----------------
__global__ void __launch_bounds__(NT, 1)
_LSTM_main(const float* __restrict__ x, float* __restrict__ out, int B) {
    extern __shared__ unsigned char smem[];
    const int tid = threadIdx.x;
    const int wid = tid >> 5;
    const int lane = tid & 31;

#pragma unroll 4
    for (int p = tid; p < WIMG / 16; p += NT)
        ((uint4*)smem)[p] = ((const uint4*)g_img)[p];
    __syncthreads();

    unsigned char* Abuf = smem + WIMG + wid * WARP_ABUF;
    const unsigned char* biasB = smem + BIAS_OFF;
    const float* fcb = (const float*)(smem + FCB_OFF);
    const float4* x4 = (const float4*)x;
    float4* o4 = (float4*)out;
    const __half2 H05 = __floats2half2_rn(0.5f, 0.5f);

    const int npair = (B + 511) >> 9;

#pragma unroll 1
    for (int it = blockIdx.x; it < npair; it += GRID) {
        const long long rowbase = (long long)it * 512 + wid * 32;

        // ---- load 32 x-rows, convert to fp16, stage (row = 128B) ----
#pragma unroll
        for (int i = 0; i < 16; i++) {
            int p = lane + i * 32;
            int r = p >> 4, c4 = p & 15;
            long long grow = rowbase + r;
            float4 v = (grow < B) ? x4[grow * 16 + c4]
                                  : make_float4(0.f, 0.f, 0.f, 0.f);
            uint32_t h0 = packh2(v.x, v.y), h1 = packh2(v.z, v.w);
            *(uint2*)(Abuf + r * AP + 8 * c4) = make_uint2(h0, h1);
        }
        __syncwarp();

        // ---- 5 LSTM layers (in-place, A in regs) + fc ----
        layer96<4>(smem, WB_L0, biasB,       Abuf, lane, H05);
        layer96<2>(smem, WB_L1, biasB + 192, Abuf, lane, H05);
        layer96<2>(smem, WB_L2, biasB + 384, Abuf, lane, H05);
        layer96<2>(smem, WB_L3, biasB + 576, Abuf, lane, H05);
        layer96<2>(smem, WB_L4, biasB + 768, Abuf, lane, H05);
        fc_stage(smem, fcb, Abuf, lane);

        // ---- coalesced f32 store ----
#pragma unroll
        for (int i = 0; i < 16; i++) {
            int p = lane + i * 32;
            int r = p >> 4, c4 = p & 15;
            long long grow = rowbase + r;
            if (grow < B)
                o4[grow * 16 + c4] = *(const float4*)(Abuf + r * AP + 16 * c4);
        }
        __syncwarp();
    }
}

// ---------------- launch ----------------
extern "C" void kernel_launch(void* const* d_in, const int* in_sizes, int n_in,
                              void* d_out, int out_size) {
    (void)n_in; (void)out_size;
    const float* x         = (const float*)d_in[0];
    const float* w_ih0     = (const float*)d_in[1];
    // d_in[2] = w_hh0      (unused: h0 == 0, T == 1)
    const float* w_ih_rest = (const float*)d_in[3];
    // d_in[4] = w_hh_rest  (unused)
    const float* b_ih      = (const float*)d_in[5];
    const float* b_hh      = (const float*)d_in[6];
    const float* fc_w      = (const float*)d_in[7];
    const float* fc_b      = (const float*)d_in[8];
    float* out = (float*)d_out;

    int B = in_sizes[0] / 64;

    _LSTM_pack<<<(20480 + 544 + 255) / 256, 256>>>(
        w_ih0, w_ih_rest, b_ih, b_hh, fc_w, fc_b);

    cudaFuncSetAttribute(_LSTM_main,
                         cudaFuncAttributeMaxDynamicSharedMemorySize, SMEM_BYTES);
    int npair = (B + 511) / 512;
    int grid = npair < GRID ? npair : GRID;
    _LSTM_main<<<grid, NT, SMEM_BYTES>>>(x, out, B);
}

// round 15
// speedup vs baseline: 1.3298x; 1.0077x over previous
#include <cuda_runtime.h>
#include <cuda_fp16.h>
#include <cstdint>

// ============================================================================
// T=1, h0=c0=0 => w_hh* unused, f-gate unused. Chain of small GEMMs on HMMA.
// R13 (kept): plain fp16 A and W, single MMA pass.
// R14 (kept): epilogue in fp16x2 (tanh.approx.f16x2), biases half2, i/o x0.5.
// R15: LSTM-layer MMAs accumulate in FP16 (mma f16.f16.f16.f16):
//   D regs arrive already packed as fp16x2 col-pairs == the h-pair layout the
//   epilogue needs -> all f32->f16 cvts deleted, C regs halved (12/ntj).
//   fc keeps f32 accumulation (its output is the final result).
// Persistent: 148 CTAs x 512 thr; warp owns 32 rows, warp-private A smem.
// ============================================================================

#define NT    512
#define GRID  148
#define AP    272
#define WIMG  42176                  // 40960 weights + 960 half biases + 256 fc
#define WARP_ABUF (32 * AP)
#define SMEM_BYTES (WIMG + 16 * WARP_ABUF)

// stage bases (bytes); per LSTM stage: [IG groups (KH*2048)][O frags (KH*1024)]
#define WB_L0 0
#define WB_L1 12288
#define WB_L2 18432
#define WB_L3 24576
#define WB_L4 30720
#define WB_FC 36864
#define BIAS_OFF 40960               // 480 halfs: [layer][i(32)|g(32)|o(32)]
#define FCB_OFF  41920               // 64 f32 fc biases

__device__ __align__(16) unsigned char g_img[WIMG];

// ---------------- fast math ----------------
__device__ __forceinline__ uint32_t tanh2(uint32_t x) {
    uint32_t y; asm("tanh.approx.f16x2 %0, %1;" : "=r"(y) : "r"(x)); return y;
}
__device__ __forceinline__ uint32_t packh2(float a, float b) {
    __half2 v = __float22half2_rn(make_float2(a, b));
    return *reinterpret_cast<uint32_t*>(&v);
}
__device__ __forceinline__ __half2 as_h2(uint32_t v) {
    return *reinterpret_cast<__half2*>(&v);
}
__device__ __forceinline__ uint32_t as_u(__half2 v) {
    return *reinterpret_cast<uint32_t*>(&v);
}

// fused fp16x2 activation for an h-PAIR; C inputs already fp16x2.
// bi2,bo2 pre-scaled by 0.5 (sig via tanh(x/2)); bg2 plain.
__device__ __forceinline__ uint32_t act_h2(
    uint32_t ci2, uint32_t cg2, uint32_t co2,
    uint32_t bi2, uint32_t bg2, uint32_t bo2, __half2 H05)
{
    __half2 ui = __hfma2(as_h2(ci2), H05, as_h2(bi2));
    __half2 si = __hfma2(as_h2(tanh2(as_u(ui))), H05, H05);
    __half2 ug = __hadd2(as_h2(cg2), as_h2(bg2));
    __half2 c2 = __hmul2(si, as_h2(tanh2(as_u(ug))));
    uint32_t tc = tanh2(as_u(c2));
    __half2 uo = __hfma2(as_h2(co2), H05, as_h2(bo2));
    __half2 so = __hfma2(as_h2(tanh2(as_u(uo))), H05, H05);
    return as_u(__hmul2(so, as_h2(tc)));
}

// ---------------- mma: fp16 in, FP16 accum (2 packed C regs) ----------------
__device__ __forceinline__ void mma_f16h(uint32_t c[2],
    const uint32_t a[4], uint32_t b0, uint32_t b1) {
    asm volatile(
        "mma.sync.aligned.m16n8k16.row.col.f16.f16.f16.f16 "
        "{%0,%1},{%2,%3,%4,%5},{%6,%7},{%0,%1};"
        : "+r"(c[0]), "+r"(c[1])
        : "r"(a[0]), "r"(a[1]), "r"(a[2]), "r"(a[3]), "r"(b0), "r"(b1));
}

// ---------------- mma: fp16 in, f32 accum (fc only) ----------------
__device__ __forceinline__ void mma_f16(float c[4],
    const uint32_t a[4], uint32_t b0, uint32_t b1) {
    asm volatile(
        "mma.sync.aligned.m16n8k16.row.col.f32.f16.f16.f32 "
        "{%0,%1,%2,%3},{%4,%5,%6,%7},{%8,%9},{%0,%1,%2,%3};"
        : "+f"(c[0]), "+f"(c[1]), "+f"(c[2]), "+f"(c[3])
        : "r"(a[0]), "r"(a[1]), "r"(a[2]), "r"(a[3]), "r"(b0), "r"(b1));
}

// ---------------- weight pack: v2 layout, plain fp16 (R13/R14) -------------
__global__ void _LSTM_pack(const float* __restrict__ w_ih0,
                           const float* __restrict__ w_ih_rest,
                           const float* __restrict__ b_ih,
                           const float* __restrict__ b_hh,
                           const float* __restrict__ fc_w,
                           const float* __restrict__ fc_b) {
    int i = blockIdx.x * blockDim.x + threadIdx.x;
    if (i < 20480) {
        int s, q;
        if (i < 6144)        { s = 0; q = i; }
        else if (i < 18432)  { s = 1 + (i - 6144) / 3072; q = (i - 6144) % 3072; }
        else                 { s = 5; q = i - 18432; }
        int fid = q >> 7, r = q & 127;
        int lane = r >> 2, reg = (r >> 1) & 1, half = r & 1;
        int n = lane >> 2;
        int kel = (lane & 3) * 2 + half + reg * 8;
        float w; unsigned dst;
        if (s < 5) {
            const int KH = (s == 0) ? 4 : 2;
            const unsigned base =
                (s == 0) ? 0u : (unsigned)(12288 + (s - 1) * 6144);
            int kidx = fid / 12, nt = fid % 12;
            int gate = nt >> 2, ntj = nt & 3;
            int k = kidx * 16 + kel;
            int j = gate * 32 + ntj * 8 + n;
            int rr = (j < 32) ? j : j + 32;
            if (s == 0) w = w_ih0[rr * 64 + k];
            else        w = w_ih_rest[(s - 1) * 4096 + rr * 32 + k];
            if (gate < 2)
                dst = base + (unsigned)(kidx * 4 + ntj) * 512
                    + lane * 16 + gate * 8 + reg * 4 + half * 2;
            else
                dst = base + (unsigned)KH * 2048 + (unsigned)(kidx * 4 + ntj) * 256
                    + lane * 8 + reg * 4 + half * 2;
            *(__half*)(g_img + dst) = __float2half_rn(w);
        } else {
            int kidx = fid / 8, nt = fid % 8;   // fid 0..15
            int k = kidx * 16 + kel;
            int j = nt * 8 + n;
            w = fc_w[j * 32 + k];
            dst = WB_FC + (unsigned)(kidx * 4 + (nt >> 1)) * 512
                + lane * 16 + (nt & 1) * 8 + reg * 4 + half * 2;
            *(__half*)(g_img + dst) = __float2half_rn(w);
        }
    } else if (i < 20480 + 480) {
        int b = i - 20480;                  // LSTM biases -> half
        int l = b / 96, j = b % 96;
        int rr = (j < 32) ? j : j + 32;
        float v = b_ih[l * 128 + rr] + b_hh[l * 128 + rr];
        if (j < 32 || j >= 64) v *= 0.5f;   // i,o rows: sig via tanh(x/2)
        *(__half*)(g_img + BIAS_OFF + b * 2) = __float2half_rn(v);
    } else if (i < 20480 + 480 + 64) {
        int b = i - 20480 - 480;            // fc biases -> f32
        *(float*)(g_img + FCB_OFF + b * 4) = fc_b[b];
    }
}

// -------- one 96-col LSTM layer: A in regs, fp16 accum, in-place h --------
// biasB: this layer's half-bias block (i at +0, g at +64, o at +128).
template<int KH>
__device__ __forceinline__ void layer96(
    const unsigned char* __restrict__ wimg, uint32_t wbase,
    const unsigned char* __restrict__ biasB, unsigned char* __restrict__ Abuf,
    int lane, __half2 H05)
{
    const int g = lane >> 2, q4 = lane & 3;
    uint32_t Ah[2][KH][4];
#pragma unroll
    for (int m = 0; m < 2; m++)
#pragma unroll
        for (int tk = 0; tk < KH; tk++) {
            const unsigned char* ab =
                Abuf + (m * 16 + g) * AP + 32 * tk + 4 * q4;
            Ah[m][tk][0] = *(const uint32_t*)ab;
            Ah[m][tk][1] = *(const uint32_t*)(ab + 8 * AP);
            Ah[m][tk][2] = *(const uint32_t*)(ab + 16);
            Ah[m][tk][3] = *(const uint32_t*)(ab + 8 * AP + 16);
        }
    __syncwarp();   // all lanes' A in regs before any h writes below

    const unsigned char* wIG = wimg + wbase + lane * 16;
    const unsigned char* wO  = wimg + wbase + KH * 2048 + lane * 8;

#pragma unroll
    for (int ntj = 0; ntj < 4; ntj++) {
        const unsigned char* aIG = wIG + ntj * 512;
        const unsigned char* aO  = wO  + ntj * 256;
        // fp16x2 accumulators: [m][reg]; reg0 = row m*16+g, reg1 = row +8
        uint32_t Ci[2][2], Cg[2][2], Co[2][2];
#pragma unroll
        for (int m = 0; m < 2; m++) {
            Ci[m][0] = 0u; Ci[m][1] = 0u;
            Cg[m][0] = 0u; Cg[m][1] = 0u;
            Co[m][0] = 0u; Co[m][1] = 0u;
        }
#pragma unroll
        for (int t = 0; t < KH; t++) {
            uint4 igf = *(const uint4*)(aIG + t * 2048);
            uint2 of  = *(const uint2*)(aO  + t * 1024);
#pragma unroll
            for (int m = 0; m < 2; m++) {
                mma_f16h(Ci[m], Ah[m][t], igf.x, igf.y);
                mma_f16h(Cg[m], Ah[m][t], igf.z, igf.w);
                mma_f16h(Co[m], Ah[m][t], of.x,  of.y);
            }
        }
        const int col = ntj * 8 + q4 * 2;
        const uint32_t bi2 = *(const uint32_t*)(biasB + col * 2);
        const uint32_t bg2 = *(const uint32_t*)(biasB + 64 + col * 2);
        const uint32_t bo2 = *(const uint32_t*)(biasB + 128 + col * 2);
#pragma unroll
        for (int m = 0; m < 2; m++) {
            unsigned char* r0 =
                Abuf + (m * 16 + g) * AP + 4 * (ntj * 4 + q4);
            *(uint32_t*)r0 =
                act_h2(Ci[m][0], Cg[m][0], Co[m][0], bi2, bg2, bo2, H05);
            *(uint32_t*)(r0 + 8 * AP) =
                act_h2(Ci[m][1], Cg[m][1], Co[m][1], bi2, bg2, bo2, H05);
        }
    }
    __syncwarp();
}

// -------- fc: A in regs; f32 accum; paired-ntj LDS.128 weights --------
__device__ __forceinline__ void fc_stage(
    const unsigned char* __restrict__ wimg,
    const float* __restrict__ fb, unsigned char* __restrict__ Abuf, int lane)
{
    const int g = lane >> 2, q4 = lane & 3;
    uint32_t Ah[2][2][4];
#pragma unroll
    for (int m = 0; m < 2; m++)
#pragma unroll
        for (int tk = 0; tk < 2; tk++) {
            const unsigned char* ab =
                Abuf + (m * 16 + g) * AP + 32 * tk + 4 * q4;
            Ah[m][tk][0] = *(const uint32_t*)ab;
            Ah[m][tk][1] = *(const uint32_t*)(ab + 8 * AP);
            Ah[m][tk][2] = *(const uint32_t*)(ab + 16);
            Ah[m][tk][3] = *(const uint32_t*)(ab + 8 * AP + 16);
        }
    __syncwarp();

    const unsigned char* wp = wimg + WB_FC + lane * 16;

#pragma unroll
    for (int np = 0; np < 4; np++) {           // ntj pairs (2np, 2np+1)
        float C0[2][4], C1[2][4];
#pragma unroll
        for (int m = 0; m < 2; m++)
#pragma unroll
            for (int q = 0; q < 4; q++) { C0[m][q] = 0.f; C1[m][q] = 0.f; }
#pragma unroll
        for (int t = 0; t < 2; t++) {
            uint4 bf = *(const uint4*)(wp + (uint32_t)(t * 4 + np) * 512);
#pragma unroll
            for (int m = 0; m < 2; m++) {
                mma_f16(C0[m], Ah[m][t], bf.x, bf.y);
                mma_f16(C1[m], Ah[m][t], bf.z, bf.w);
            }
        }
#pragma unroll
        for (int half = 0; half < 2; half++) {
            float (*C)[4] = half ? C1 : C0;
            const int col = (np * 2 + half) * 8 + q4 * 2;
            const float b0 = fb[col], b1 = fb[col + 1];
#pragma unroll
            for (int m = 0; m < 2; m++) {
                float* r0 = (float*)(Abuf + (m * 16 + g) * AP + 4 * col);
                float* r1 = (float*)((unsigned char*)r0 + 8 * AP);
                r0[0] = C[m][0] + b0; r0[1] = C[m][1] + b1;
                r1[0] = C[m][2] + b0; r1[1] = C[m][3] + b1;
            }
        }
    }
    __syncwarp();
}

// ---------------- main persistent kernel ----------------
__global__ void __launch_bounds__(NT, 1)
_LSTM_main(const float* __restrict__ x, float* __restrict__ out, int B) {
    extern __shared__ unsigned char smem[];
    const int tid = threadIdx.x;
    const int wid = tid >> 5;
    const int lane = tid & 31;

#pragma unroll 4
    for (int p = tid; p < WIMG / 16; p += NT)
        ((uint4*)smem)[p] = ((const uint4*)g_img)[p];
    __syncthreads();

    unsigned char* Abuf = smem + WIMG + wid * WARP_ABUF;
    const unsigned char* biasB = smem + BIAS_OFF;
    const float* fcb = (const float*)(smem + FCB_OFF);
    const float4* x4 = (const float4*)x;
    float4* o4 = (float4*)out;
    const __half2 H05 = __floats2half2_rn(0.5f, 0.5f);

    const int npair = (B + 511) >> 9;

#pragma unroll 1
    for (int it = blockIdx.x; it < npair; it += GRID) {
        const long long rowbase = (long long)it * 512 + wid * 32;

        // ---- load 32 x-rows, convert to fp16, stage (row = 128B) ----
#pragma unroll
        for (int i = 0; i < 16; i++) {
            int p = lane + i * 32;
            int r = p >> 4, c4 = p & 15;
            long long grow = rowbase + r;
            float4 v = (grow < B) ? x4[grow * 16 + c4]
                                  : make_float4(0.f, 0.f, 0.f, 0.f);
            uint32_t h0 = packh2(v.x, v.y), h1 = packh2(v.z, v.w);
            *(uint2*)(Abuf + r * AP + 8 * c4) = make_uint2(h0, h1);
        }
        __syncwarp();

        // ---- 5 LSTM layers (in-place, A in regs, fp16 accum) + fc ----
        layer96<4>(smem, WB_L0, biasB,       Abuf, lane, H05);
        layer96<2>(smem, WB_L1, biasB + 192, Abuf, lane, H05);
        layer96<2>(smem, WB_L2, biasB + 384, Abuf, lane, H05);
        layer96<2>(smem, WB_L3, biasB + 576, Abuf, lane, H05);
        layer96<2>(smem, WB_L4, biasB + 768, Abuf, lane, H05);
        fc_stage(smem, fcb, Abuf, lane);

        // ---- coalesced f32 store ----
#pragma unroll
        for (int i = 0; i < 16; i++) {
            int p = lane + i * 32;
            int r = p >> 4, c4 = p & 15;
            long long grow = rowbase + r;
            if (grow < B)
                o4[grow * 16 + c4] = *(const float4*)(Abuf + r * AP + 16 * c4);
        }
        __syncwarp();
    }
}

// ---------------- launch ----------------
extern "C" void kernel_launch(void* const* d_in, const int* in_sizes, int n_in,
                              void* d_out, int out_size) {
    (void)n_in; (void)out_size;
    const float* x         = (const float*)d_in[0];
    const float* w_ih0     = (const float*)d_in[1];
    // d_in[2] = w_hh0      (unused: h0 == 0, T == 1)
    const float* w_ih_rest = (const float*)d_in[3];
    // d_in[4] = w_hh_rest  (unused)
    const float* b_ih      = (const float*)d_in[5];
    const float* b_hh      = (const float*)d_in[6];
    const float* fc_w      = (const float*)d_in[7];
    const float* fc_b      = (const float*)d_in[8];
    float* out = (float*)d_out;

    int B = in_sizes[0] / 64;

    _LSTM_pack<<<(20480 + 544 + 255) / 256, 256>>>(
        w_ih0, w_ih_rest, b_ih, b_hh, fc_w, fc_b);

    cudaFuncSetAttribute(_LSTM_main,
                         cudaFuncAttributeMaxDynamicSharedMemorySize, SMEM_BYTES);
    int npair = (B + 511) / 512;
    int grid = npair < GRID ? npair : GRID;
    _LSTM_main<<<grid, NT, SMEM_BYTES>>>(x, out, B);
}